// round 14
// baseline (speedup 1.0000x reference)
#include <cuda_runtime.h>
#include <cstdint>

#define T_MAX   8192
#define DIN     4096
#define DOUT    4096
#define NE      8
#define NPAIR   28
#define SCALING 2.0f            // 16.0 / r with r=8
#define TW      4               // tokens per warp in phase A
#define ACH     256             // phase A cols per chunk
#define NCHA    (DIN / ACH)     // 16 chunks
#define WBUF    16384           // per-buffer bytes: w only (8 pr x 256 col u64)
#define YDIM    10              // phase A grid.y — 28*10=280 CTAs ~= one full wave (296 slots)

// -------- scratch (device globals; no allocations allowed) --------
__device__ int    g_cnt[NPAIR];                 // B-pair counts
__device__ int    g_list[NPAIR * T_MAX];        // B-pair token lists
__device__ int    g_cntA[NPAIR];                // A-pair counts
__device__ int    g_listA[NPAIR * T_MAX];       // A-pair token lists
__device__ float2 g_wA[T_MAX];                  // A weights, sorted (lo, hi)
__device__ float2 g_cB[T_MAX];                  // B coeffs (incl. SCALING), sorted
__device__ __align__(16) float g_smid2[T_MAX * 32];   // dup'd scaled s: (v,v) pairs
__device__ float  g_part[64 * 16];
// paired Wa: g_wa2[(e*4+q)*4096 + c] as u64 = (Wa[e][2q][c], Wa[e][2q+1][c])
__device__ __align__(16) float g_wa2[NE * 4 * DIN * 2];
// transposed Wb: g_wb2[e][r][col]
__device__ __align__(16) float g_wb2[NE * 8 * DOUT];

// -------- helpers --------
__device__ __forceinline__ void ffma2(uint64_t& acc, uint64_t a, uint64_t b) {
    asm("fma.rn.f32x2 %0, %1, %2, %0;" : "+l"(acc) : "l"(a), "l"(b));
}
__device__ __forceinline__ uint64_t add2(uint64_t a, uint64_t b) {
    uint64_t r;
    asm("add.rn.f32x2 %0, %1, %2;" : "=l"(r) : "l"(a), "l"(b));
    return r;
}
__device__ __forceinline__ float2 u2f(uint64_t v) {
    float2 f;
    f.x = __uint_as_float((unsigned)(v & 0xffffffffu));
    f.y = __uint_as_float((unsigned)(v >> 32));
    return f;
}
__device__ __forceinline__ uint64_t dup2(float v) {
    uint64_t r; unsigned u = __float_as_uint(v);
    asm("mov.b64 %0, {%1, %2};" : "=l"(r) : "r"(u), "r"(u));
    return r;
}
__device__ __forceinline__ uint64_t pack2(float a, float b) {
    uint64_t r;
    asm("mov.b64 %0, {%1, %2};" : "=l"(r) : "r"(__float_as_uint(a)), "r"(__float_as_uint(b)));
    return r;
}
__device__ __forceinline__ unsigned sw(unsigned off) { return off ^ ((off >> 3) & 0x70u); }
__device__ __forceinline__ void cpasync16(unsigned dst, const void* src) {
    asm volatile("cp.async.cg.shared.global [%0], [%1], 16;" :: "r"(dst), "l"(src) : "memory");
}
__device__ __forceinline__ void cpcommit() {
    asm volatile("cp.async.commit_group;" ::: "memory");
}
__device__ __forceinline__ void cpwait0() {
    asm volatile("cp.async.wait_group 0;" ::: "memory");
}

// -------- fused prep+route kernel --------
// blocks [0,128): paired Wa; [128,384): transposed Wb; [384,...): routing.
__device__ __forceinline__ void do_prepA(const float* __restrict__ Wa, int bid) {
    int idx = bid * 256 + threadIdx.x;             // 32768 tasks: e4q(32) x c4(1024)
    int e4q = idx >> 10, c4 = idx & 1023;
    int e = e4q >> 2, q = e4q & 3;
    float4 a = *(const float4*)(Wa + ((size_t)(e * 8 + 2 * q) * DIN + c4 * 4));
    float4 b = *(const float4*)(Wa + ((size_t)(e * 8 + 2 * q + 1) * DIN + c4 * 4));
    float* dst = g_wa2 + ((size_t)e4q * DIN + c4 * 4) * 2;
    *(float4*)(dst)     = make_float4(a.x, b.x, a.y, b.y);
    *(float4*)(dst + 4) = make_float4(a.z, b.z, a.w, b.w);
}
__device__ __forceinline__ void do_prepB(const float* __restrict__ Wb, int bid) {
    int idx = bid * 256 + threadIdx.x;             // 65536 tasks: e(8) x r(8) x c4(1024)
    int e = idx >> 13, r = (idx >> 10) & 7, c4 = idx & 1023;
    const float* src = Wb + (size_t)e * 32768 + (size_t)c4 * 32 + r;
    float4 v = make_float4(src[0], src[8], src[16], src[24]);
    *(float4*)(g_wb2 + (size_t)e * 32768 + (size_t)r * 4096 + c4 * 4) = v;
}

__global__ void k_prep_route(const float* __restrict__ Wa, const float* __restrict__ Wb,
                             const float* __restrict__ la, const float* __restrict__ lb, int T) {
    if (blockIdx.x < 128) { do_prepA(Wa, blockIdx.x); return; }
    if (blockIdx.x < 384) { do_prepB(Wb, blockIdx.x - 128); return; }
    int bid = blockIdx.x - 384;
    int t = bid * 256 + threadIdx.x;
    float pa[8], pb[8];
#pragma unroll
    for (int i = 0; i < 8; i++) { pa[i] = 0.f; pb[i] = 0.f; }

    if (t < T) {
        // ---- A router ----
        float l[8];
        float4 u0 = *(const float4*)(la + (size_t)t * 8);
        float4 u1 = *(const float4*)(la + (size_t)t * 8 + 4);
        l[0]=u0.x; l[1]=u0.y; l[2]=u0.z; l[3]=u0.w;
        l[4]=u1.x; l[5]=u1.y; l[6]=u1.z; l[7]=u1.w;
        int i0 = 0; float v0 = l[0];
#pragma unroll
        for (int i = 1; i < 8; i++) if (l[i] > v0) { v0 = l[i]; i0 = i; }
        int i1 = -1; float v1 = -1e30f;
#pragma unroll
        for (int i = 0; i < 8; i++) if (i != i0 && l[i] > v1) { v1 = l[i]; i1 = i; }
        float e1 = expf(v1 - v0);
        float inv01 = 1.f / (1.f + e1);
        float wa0 = inv01, wa1 = e1 * inv01;
        float s = 0.f;
#pragma unroll
        for (int i = 0; i < 8; i++) { pa[i] = expf(l[i] - v0); s += pa[i]; }
        float invs = 1.f / s;
#pragma unroll
        for (int i = 0; i < 8; i++) pa[i] *= invs;
        if (i0 > i1) { int ti = i0; i0 = i1; i1 = ti; float tw = wa0; wa0 = wa1; wa1 = tw; }
        g_wA[t] = make_float2(wa0, wa1);
        int prA = 7 * i0 - (i0 * (i0 - 1)) / 2 + (i1 - i0 - 1);
        int posA = atomicAdd(&g_cntA[prA], 1);
        g_listA[prA * T_MAX + posA] = t;

        // ---- B router ----
        float m[8];
        float4 b0 = *(const float4*)(lb + (size_t)t * 8);
        float4 b1 = *(const float4*)(lb + (size_t)t * 8 + 4);
        m[0]=b0.x; m[1]=b0.y; m[2]=b0.z; m[3]=b0.w;
        m[4]=b1.x; m[5]=b1.y; m[6]=b1.z; m[7]=b1.w;
        int j0 = 0; float w0 = m[0];
#pragma unroll
        for (int i = 1; i < 8; i++) if (m[i] > w0) { w0 = m[i]; j0 = i; }
        int j1 = -1; float w1 = -1e30f;
#pragma unroll
        for (int i = 0; i < 8; i++) if (i != j0 && m[i] > w1) { w1 = m[i]; j1 = i; }
        float eb = expf(w1 - w0);
        float invb = 1.f / (1.f + eb);
        float c0 = SCALING * invb;
        float c1 = SCALING * eb * invb;
        s = 0.f;
#pragma unroll
        for (int i = 0; i < 8; i++) { pb[i] = expf(m[i] - w0); s += pb[i]; }
        invs = 1.f / s;
#pragma unroll
        for (int i = 0; i < 8; i++) pb[i] *= invs;
        if (j0 > j1) { int tj = j0; j0 = j1; j1 = tj; float tc = c0; c0 = c1; c1 = tc; }
        g_cB[t] = make_float2(c0, c1);
        int pr = 7 * j0 - (j0 * (j0 - 1)) / 2 + (j1 - j0 - 1);
        int pos = atomicAdd(&g_cnt[pr], 1);
        g_list[pr * T_MAX + pos] = t;
    }

    // deterministic block reduction of prob partials
    __shared__ float wred[8][16];
    int lane = threadIdx.x & 31, wid = threadIdx.x >> 5;
#pragma unroll
    for (int j = 0; j < 16; j++) {
        float v = (j < 8) ? pa[j] : pb[j - 8];
#pragma unroll
        for (int o = 16; o > 0; o >>= 1) v += __shfl_down_sync(0xffffffffu, v, o);
        if (lane == 0) wred[wid][j] = v;
    }
    __syncthreads();
    if (threadIdx.x < 16) {
        float acc = 0.f;
#pragma unroll
        for (int w = 0; w < 8; w++) acc += wred[w][threadIdx.x];
        g_part[bid * 16 + threadIdx.x] = acc;
    }
}

// -------- kernel 2: phase A — w via cp.async smem (2 buf), x via register-prefetched LDG --------
// grid (28 pairs, YDIM tiles), 256 threads (8 warps x TW=4 tokens = 32 tokens/CTA).
// smem: 2 x 16KB weight buffers (8 pr x 256 col u64, swizzled).
__global__ __launch_bounds__(256, 2) void k_phaseA(const float* __restrict__ x) {
    int pair = blockIdx.x;
    int cnt = g_cntA[pair];

    int lo = 0, rem = pair;
#pragma unroll
    for (int l = 0; l < 7; l++) { int n = 7 - l; if (rem < n) { lo = l; break; } rem -= n; }
    int hi = lo + 1 + rem;
    int lo4 = lo * 4, hi4 = hi * 4;

    extern __shared__ __align__(16) char smc[];
    unsigned sbase = (unsigned)__cvta_generic_to_shared(smc);
    __shared__ int t_s[32];

    int tid = threadIdx.x, warp = tid >> 5, lane = tid & 31;

    // w staging tasks (4 float4 per thread per chunk): idx in [0,1024): pr=idx>>7, c16=idx&127
    unsigned wdst[4]; size_t wsrc[4];
#pragma unroll
    for (int k = 0; k < 4; k++) {
        int idx = k * 256 + tid;
        int pr = idx >> 7, c16 = idx & 127;
        int e4q = (pr < 4) ? (lo4 + pr) : (hi4 + pr - 4);
        wsrc[k] = (size_t)e4q * (DIN * 2) + c16 * 4;     // float offset; + ch*512
        wdst[k] = sw((unsigned)(pr * 2048 + c16 * 16));
    }

    for (int tbase = blockIdx.y * 32; tbase < cnt; tbase += YDIM * 32) {
        __syncthreads();
        if (tid < 32) {
            int ti = tbase + tid;
            t_s[tid] = g_listA[pair * T_MAX + ((ti < cnt) ? ti : 0)];
        }
        __syncthreads();

        // per-token x base pointers (this thread covers cols lane*4 + it*128 + ch*256)
        const float* xp[TW];
#pragma unroll
        for (int j = 0; j < TW; j++)
            xp[j] = x + (size_t)t_s[warp * TW + j] * DIN + lane * 4;

        int tokv = tbase + warp * TW;

        uint64_t acc[TW][8];
#pragma unroll
        for (int j = 0; j < TW; j++)
#pragma unroll
            for (int p = 0; p < 8; p++) acc[j][p] = 0ull;

        // prologue: stage w chunk 0; prefetch x it0 of chunk 0
#pragma unroll
        for (int k = 0; k < 4; k++)
            cpasync16(sbase + wdst[k], g_wa2 + wsrc[k]);
        cpcommit();
        float4 x0[TW];
#pragma unroll
        for (int j = 0; j < TW; j++) x0[j] = *(const float4*)(xp[j]);

        for (int ch = 0; ch < NCHA; ++ch) {
            cpwait0();
            __syncthreads();
            if (ch + 1 < NCHA) {
                unsigned nb = (unsigned)(((ch + 1) & 1) * WBUF);
#pragma unroll
                for (int k = 0; k < 4; k++)
                    cpasync16(sbase + nb + wdst[k], g_wa2 + wsrc[k] + (ch + 1) * 512);
                cpcommit();
            }
            unsigned bufb = (unsigned)((ch & 1) * WBUF);

            // issue x loads for it1 of this chunk now (consumed ~1K cyc later)
            float4 x1[TW];
#pragma unroll
            for (int j = 0; j < TW; j++)
                x1[j] = *(const float4*)(xp[j] + ch * ACH + 128);

            // ---- it0: compute from prefetched x0 ----
            {
                uint64_t dx[TW][4];
#pragma unroll
                for (int j = 0; j < TW; j++) {
                    dx[j][0] = dup2(x0[j].x); dx[j][1] = dup2(x0[j].y);
                    dx[j][2] = dup2(x0[j].z); dx[j][3] = dup2(x0[j].w);
                }
#pragma unroll
                for (int pr = 0; pr < 8; ++pr) {
                    unsigned o0 = (unsigned)(pr * 2048 + lane * 32);
                    unsigned sA = bufb + sw(o0), sB = bufb + sw(o0 + 16);
                    uint64_t w0, w1, w2, w3;
                    asm("ld.shared.v2.b64 {%0,%1},[%2];" : "=l"(w0), "=l"(w1) : "r"(sbase + sA));
                    asm("ld.shared.v2.b64 {%0,%1},[%2];" : "=l"(w2), "=l"(w3) : "r"(sbase + sB));
#pragma unroll
                    for (int j = 0; j < TW; j++) {
                        ffma2(acc[j][pr], w0, dx[j][0]);
                        ffma2(acc[j][pr], w1, dx[j][1]);
                        ffma2(acc[j][pr], w2, dx[j][2]);
                        ffma2(acc[j][pr], w3, dx[j][3]);
                    }
                }
            }

            // prefetch x it0 of next chunk (x0 regs free now)
            if (ch + 1 < NCHA) {
#pragma unroll
                for (int j = 0; j < TW; j++)
                    x0[j] = *(const float4*)(xp[j] + (ch + 1) * ACH);
            }

            // ---- it1: compute from x1 ----
            {
                uint64_t dx[TW][4];
#pragma unroll
                for (int j = 0; j < TW; j++) {
                    dx[j][0] = dup2(x1[j].x); dx[j][1] = dup2(x1[j].y);
                    dx[j][2] = dup2(x1[j].z); dx[j][3] = dup2(x1[j].w);
                }
#pragma unroll
                for (int pr = 0; pr < 8; ++pr) {
                    unsigned o0 = (unsigned)(pr * 2048 + 1024 + lane * 32);
                    unsigned sA = bufb + sw(o0), sB = bufb + sw(o0 + 16);
                    uint64_t w0, w1, w2, w3;
                    asm("ld.shared.v2.b64 {%0,%1},[%2];" : "=l"(w0), "=l"(w1) : "r"(sbase + sA));
                    asm("ld.shared.v2.b64 {%0,%1},[%2];" : "=l"(w2), "=l"(w3) : "r"(sbase + sB));
#pragma unroll
                    for (int j = 0; j < TW; j++) {
                        ffma2(acc[j][pr], w0, dx[j][0]);
                        ffma2(acc[j][pr], w1, dx[j][1]);
                        ffma2(acc[j][pr], w2, dx[j][2]);
                        ffma2(acc[j][pr], w3, dx[j][3]);
                    }
                }
            }
        }

        // per-token cross-lane reduce + dup'd smid write
#pragma unroll
        for (int j = 0; j < TW; j++) {
            if (tokv + j >= cnt) continue;      // warp-uniform
            float a[16];
#pragma unroll
            for (int p = 0; p < 8; p++) {
                float2 f = u2f(acc[j][p]);
                a[2 * p] = f.x; a[2 * p + 1] = f.y;
            }
#pragma unroll
            for (int o = 16; o > 0; o >>= 1)
#pragma unroll
                for (int i = 0; i < 16; i++) a[i] += __shfl_down_sync(0xffffffffu, a[i], o);
            if (lane == 0) {
                int t = t_s[warp * TW + j];
                float2 wA = g_wA[t], cB = g_cB[t];
                float mid[8];
#pragma unroll
                for (int i = 0; i < 8; i++) mid[i] = wA.x * a[i] + wA.y * a[8 + i];
                float* d = g_smid2 + (size_t)t * 32;
#pragma unroll
                for (int h = 0; h < 2; h++) {
                    float c = h ? cB.y : cB.x;
#pragma unroll
                    for (int rp = 0; rp < 4; rp++) {
                        float v0 = c * mid[2 * rp], v1 = c * mid[2 * rp + 1];
                        *(float4*)(d + h * 16 + rp * 4) = make_float4(v0, v0, v1, v1);
                    }
                }
            }
        }
    }
}

// -------- kernel 3: phase B — col-paired accumulators, transposed Wb, token-split x4 --------
// grid (28 pairs, 8 col-blocks of 512, 4 token-slices), 128 threads, thread = 4 cols.
__global__ __launch_bounds__(128) void k_phaseB(float* __restrict__ out) {
    int pair = blockIdx.x, cb = blockIdx.y, q = blockIdx.z;
    int tid = threadIdx.x;

    int lo = 0, rem = pair;
#pragma unroll
    for (int l = 0; l < 7; l++) { int n = 7 - l; if (rem < n) { lo = l; break; } rem -= n; }
    int hi = lo + 1 + rem;

    int count = g_cnt[pair];
    int tstart = (count * q) >> 2, tend = (count * (q + 1)) >> 2;
    const int* lst = g_list + pair * T_MAX;
    int o0 = cb * 512 + tid * 4;

    // weights: w01[r] = cols (o0, o0+1), w23[r] = cols (o0+2, o0+3); r 0..7 lo, 8..15 hi
    uint64_t w01[16], w23[16];
#pragma unroll
    for (int r = 0; r < 16; r++) {
        int e = (r < 8) ? lo : hi;
        float4 v = *(const float4*)(g_wb2 + (size_t)e * 32768 + (size_t)(r & 7) * 4096 + o0);
        w01[r] = pack2(v.x, v.y);
        w23[r] = pack2(v.z, v.w);
    }

    __shared__ __align__(16) float s_s[64 * 32];
    __shared__ int t_s[64];

    for (int base = tstart; base < tend; base += 64) {
        int n = min(64, tend - base);
        __syncthreads();
        if (tid < n) t_s[tid] = lst[base + tid];
        for (int v = tid; v < n * 8; v += 128) {
            int tk = v >> 3, part = v & 7;
            int t = lst[base + tk];
            *(float4*)(s_s + tk * 32 + part * 4) =
                *(const float4*)(g_smid2 + (size_t)t * 32 + part * 4);
        }
        __syncthreads();

        int i = 0;
        for (; i + 1 < n; i += 2) {
            const float* sp0 = s_s + i * 32;
            const float* sp1 = sp0 + 32;
            uint64_t aA0 = 0, aA1 = 0, aB0 = 0, aB1 = 0;
            uint64_t bA0 = 0, bA1 = 0, bB0 = 0, bB1 = 0;
#pragma unroll
            for (int rp = 0; rp < 8; rp++) {
                ulonglong2 s0 = *(const ulonglong2*)(sp0 + 4 * rp);
                ulonglong2 s1 = *(const ulonglong2*)(sp1 + 4 * rp);
                ffma2(aA0, s0.x, w01[2 * rp]);  ffma2(aA1, s0.y, w01[2 * rp + 1]);
                ffma2(aB0, s0.x, w23[2 * rp]);  ffma2(aB1, s0.y, w23[2 * rp + 1]);
                ffma2(bA0, s1.x, w01[2 * rp]);  ffma2(bA1, s1.y, w01[2 * rp + 1]);
                ffma2(bB0, s1.x, w23[2 * rp]);  ffma2(bB1, s1.y, w23[2 * rp + 1]);
            }
            float2 fa = u2f(add2(aA0, aA1)), fb = u2f(add2(aB0, aB1));
            *(float4*)(out + (size_t)t_s[i] * DOUT + o0) = make_float4(fa.x, fa.y, fb.x, fb.y);
            float2 ga = u2f(add2(bA0, bA1)), gb = u2f(add2(bB0, bB1));
            *(float4*)(out + (size_t)t_s[i + 1] * DOUT + o0) = make_float4(ga.x, ga.y, gb.x, gb.y);
        }
        if (i < n) {
            const float* sp0 = s_s + i * 32;
            uint64_t aA0 = 0, aA1 = 0, aB0 = 0, aB1 = 0;
#pragma unroll
            for (int rp = 0; rp < 8; rp++) {
                ulonglong2 s0 = *(const ulonglong2*)(sp0 + 4 * rp);
                ffma2(aA0, s0.x, w01[2 * rp]);  ffma2(aA1, s0.y, w01[2 * rp + 1]);
                ffma2(aB0, s0.x, w23[2 * rp]);  ffma2(aB1, s0.y, w23[2 * rp + 1]);
            }
            float2 fa = u2f(add2(aA0, aA1)), fb = u2f(add2(aB0, aB1));
            *(float4*)(out + (size_t)t_s[i] * DOUT + o0) = make_float4(fa.x, fa.y, fb.x, fb.y);
        }
    }
}

// -------- kernel 4: aux losses (parallel reduction) + counter reset --------
__global__ void k_aux(float* __restrict__ out2, int T, int nblk) {
    __shared__ float red[16][17];
    __shared__ float p[16];
    int j = threadIdx.x & 15, g = threadIdx.x >> 4;    // 16 groups x 16 cols
    float s = 0.f;
    for (int b = g; b < nblk; b += 16) s += g_part[b * 16 + j];
    red[g][j] = s;
    __syncthreads();
    if (threadIdx.x < 16) {
        float acc = 0.f;
#pragma unroll
        for (int gg = 0; gg < 16; gg++) acc += red[gg][threadIdx.x];
        p[threadIdx.x] = acc / (float)T;
    }
    __syncthreads();
    if (threadIdx.x == 0) {
        float m = 0.f;
#pragma unroll
        for (int i = 0; i < 8; i++) m += p[i];
        m *= 0.125f;
        float v = 0.f;
#pragma unroll
        for (int i = 0; i < 8; i++) { float d = p[i] - m; v += d * d; }
        out2[0] = 8.f * (v / 7.f);

        float m2 = 0.f;
#pragma unroll
        for (int i = 8; i < 16; i++) m2 += p[i];
        m2 *= 0.125f;
        float v2 = 0.f;
#pragma unroll
        for (int i = 8; i < 16; i++) { float d = p[i] - m2; v2 += d * d; }
        out2[1] = 8.f * (v2 / 7.f);
    }
    // reset pair counters for the next graph replay (initial state is static zero)
    if (threadIdx.x < NPAIR) { g_cnt[threadIdx.x] = 0; g_cntA[threadIdx.x] = 0; }
}

// -------- launcher --------
extern "C" void kernel_launch(void* const* d_in, const int* in_sizes, int n_in,
                              void* d_out, int out_size) {
    const float* x  = (const float*)d_in[0];
    const float* la = (const float*)d_in[1];
    const float* lb = (const float*)d_in[2];
    const float* Wa = (const float*)d_in[3];
    const float* Wb = (const float*)d_in[4];
    float* out = (float*)d_out;

    int T = in_sizes[1] / NE;           // 8192
    if (T > T_MAX) return;
    int nblk = (T + 255) / 256;

    static int smem_set = 0;
    int smemA = 2 * WBUF;               // 32 KB
    if (!smem_set) {
        cudaFuncSetAttribute(k_phaseA, cudaFuncAttributeMaxDynamicSharedMemorySize, smemA);
        smem_set = 1;
    }

    k_prep_route<<<384 + nblk, 256>>>(Wa, Wb, la, lb, T);
    dim3 gA(NPAIR, YDIM);
    k_phaseA<<<gA, 256, smemA>>>(x);
    dim3 gB(NPAIR, DOUT / 512, 4);
    k_phaseB<<<gB, 128>>>(out);
    k_aux<<<1, 256>>>(out + (size_t)out_size - 2, T, nblk);
}

// round 15
// speedup vs baseline: 1.2808x; 1.2808x over previous
#include <cuda_runtime.h>
#include <cstdint>

#define T_MAX   8192
#define DIN     4096
#define DOUT    4096
#define NE      8
#define NPAIR   28
#define SCALING 2.0f            // 16.0 / r with r=8
#define TW      4               // tokens per warp in phase A
#define ACH     256             // phase A cols per chunk
#define NCHA    (DIN / ACH)     // 16 chunks
#define WBUF    16384           // per-buffer bytes: w only (8 pr x 256 col u64)

// -------- scratch (device globals; no allocations allowed) --------
__device__ int    g_cnt[NPAIR];                 // B-pair counts
__device__ int    g_list[NPAIR * T_MAX];        // B-pair token lists
__device__ int    g_cntA[NPAIR];                // A-pair counts
__device__ int    g_listA[NPAIR * T_MAX];       // A-pair token lists
__device__ float2 g_wA[T_MAX];                  // A weights, sorted (lo, hi)
__device__ float2 g_cB[T_MAX];                  // B coeffs (incl. SCALING), sorted
__device__ __align__(16) float g_smid2[T_MAX * 32];   // dup'd scaled s: (v,v) pairs
__device__ float  g_part[64 * 16];
// paired Wa: g_wa2[(e*4+q)*4096 + c] as u64 = (Wa[e][2q][c], Wa[e][2q+1][c])
__device__ __align__(16) float g_wa2[NE * 4 * DIN * 2];
// transposed Wb: g_wb2[e][r][col]
__device__ __align__(16) float g_wb2[NE * 8 * DOUT];

// -------- helpers --------
__device__ __forceinline__ void ffma2(uint64_t& acc, uint64_t a, uint64_t b) {
    asm("fma.rn.f32x2 %0, %1, %2, %0;" : "+l"(acc) : "l"(a), "l"(b));
}
__device__ __forceinline__ uint64_t add2(uint64_t a, uint64_t b) {
    uint64_t r;
    asm("add.rn.f32x2 %0, %1, %2;" : "=l"(r) : "l"(a), "l"(b));
    return r;
}
__device__ __forceinline__ float2 u2f(uint64_t v) {
    float2 f;
    f.x = __uint_as_float((unsigned)(v & 0xffffffffu));
    f.y = __uint_as_float((unsigned)(v >> 32));
    return f;
}
__device__ __forceinline__ uint64_t dup2(float v) {
    uint64_t r; unsigned u = __float_as_uint(v);
    asm("mov.b64 %0, {%1, %2};" : "=l"(r) : "r"(u), "r"(u));
    return r;
}
__device__ __forceinline__ uint64_t pack2(float a, float b) {
    uint64_t r;
    asm("mov.b64 %0, {%1, %2};" : "=l"(r) : "r"(__float_as_uint(a)), "r"(__float_as_uint(b)));
    return r;
}
__device__ __forceinline__ unsigned sw(unsigned off) { return off ^ ((off >> 3) & 0x70u); }
__device__ __forceinline__ void cpasync16(unsigned dst, const void* src) {
    asm volatile("cp.async.cg.shared.global [%0], [%1], 16;" :: "r"(dst), "l"(src) : "memory");
}
__device__ __forceinline__ void cpcommit() {
    asm volatile("cp.async.commit_group;" ::: "memory");
}
__device__ __forceinline__ void cpwait0() {
    asm volatile("cp.async.wait_group 0;" ::: "memory");
}

// -------- fused prep+route kernel --------
// blocks [0,128): paired Wa; [128,384): transposed Wb; [384,...): routing.
__device__ __forceinline__ void do_prepA(const float* __restrict__ Wa, int bid) {
    int idx = bid * 256 + threadIdx.x;             // 32768 tasks: e4q(32) x c4(1024)
    int e4q = idx >> 10, c4 = idx & 1023;
    int e = e4q >> 2, q = e4q & 3;
    float4 a = *(const float4*)(Wa + ((size_t)(e * 8 + 2 * q) * DIN + c4 * 4));
    float4 b = *(const float4*)(Wa + ((size_t)(e * 8 + 2 * q + 1) * DIN + c4 * 4));
    float* dst = g_wa2 + ((size_t)e4q * DIN + c4 * 4) * 2;
    *(float4*)(dst)     = make_float4(a.x, b.x, a.y, b.y);
    *(float4*)(dst + 4) = make_float4(a.z, b.z, a.w, b.w);
}
__device__ __forceinline__ void do_prepB(const float* __restrict__ Wb, int bid) {
    int idx = bid * 256 + threadIdx.x;             // 65536 tasks: e(8) x r(8) x c4(1024)
    int e = idx >> 13, r = (idx >> 10) & 7, c4 = idx & 1023;
    const float* src = Wb + (size_t)e * 32768 + (size_t)c4 * 32 + r;
    float4 v = make_float4(src[0], src[8], src[16], src[24]);
    *(float4*)(g_wb2 + (size_t)e * 32768 + (size_t)r * 4096 + c4 * 4) = v;
}

__global__ void k_prep_route(const float* __restrict__ Wa, const float* __restrict__ Wb,
                             const float* __restrict__ la, const float* __restrict__ lb, int T) {
    if (blockIdx.x < 128) { do_prepA(Wa, blockIdx.x); return; }
    if (blockIdx.x < 384) { do_prepB(Wb, blockIdx.x - 128); return; }
    int bid = blockIdx.x - 384;
    int t = bid * 256 + threadIdx.x;
    float pa[8], pb[8];
#pragma unroll
    for (int i = 0; i < 8; i++) { pa[i] = 0.f; pb[i] = 0.f; }

    if (t < T) {
        // ---- A router ----
        float l[8];
        float4 u0 = *(const float4*)(la + (size_t)t * 8);
        float4 u1 = *(const float4*)(la + (size_t)t * 8 + 4);
        l[0]=u0.x; l[1]=u0.y; l[2]=u0.z; l[3]=u0.w;
        l[4]=u1.x; l[5]=u1.y; l[6]=u1.z; l[7]=u1.w;
        int i0 = 0; float v0 = l[0];
#pragma unroll
        for (int i = 1; i < 8; i++) if (l[i] > v0) { v0 = l[i]; i0 = i; }
        int i1 = -1; float v1 = -1e30f;
#pragma unroll
        for (int i = 0; i < 8; i++) if (i != i0 && l[i] > v1) { v1 = l[i]; i1 = i; }
        float e1 = expf(v1 - v0);
        float inv01 = 1.f / (1.f + e1);
        float wa0 = inv01, wa1 = e1 * inv01;
        float s = 0.f;
#pragma unroll
        for (int i = 0; i < 8; i++) { pa[i] = expf(l[i] - v0); s += pa[i]; }
        float invs = 1.f / s;
#pragma unroll
        for (int i = 0; i < 8; i++) pa[i] *= invs;
        if (i0 > i1) { int ti = i0; i0 = i1; i1 = ti; float tw = wa0; wa0 = wa1; wa1 = tw; }
        g_wA[t] = make_float2(wa0, wa1);
        int prA = 7 * i0 - (i0 * (i0 - 1)) / 2 + (i1 - i0 - 1);
        int posA = atomicAdd(&g_cntA[prA], 1);
        g_listA[prA * T_MAX + posA] = t;

        // ---- B router ----
        float m[8];
        float4 b0 = *(const float4*)(lb + (size_t)t * 8);
        float4 b1 = *(const float4*)(lb + (size_t)t * 8 + 4);
        m[0]=b0.x; m[1]=b0.y; m[2]=b0.z; m[3]=b0.w;
        m[4]=b1.x; m[5]=b1.y; m[6]=b1.z; m[7]=b1.w;
        int j0 = 0; float w0 = m[0];
#pragma unroll
        for (int i = 1; i < 8; i++) if (m[i] > w0) { w0 = m[i]; j0 = i; }
        int j1 = -1; float w1 = -1e30f;
#pragma unroll
        for (int i = 0; i < 8; i++) if (i != j0 && m[i] > w1) { w1 = m[i]; j1 = i; }
        float eb = expf(w1 - w0);
        float invb = 1.f / (1.f + eb);
        float c0 = SCALING * invb;
        float c1 = SCALING * eb * invb;
        s = 0.f;
#pragma unroll
        for (int i = 0; i < 8; i++) { pb[i] = expf(m[i] - w0); s += pb[i]; }
        invs = 1.f / s;
#pragma unroll
        for (int i = 0; i < 8; i++) pb[i] *= invs;
        if (j0 > j1) { int tj = j0; j0 = j1; j1 = tj; float tc = c0; c0 = c1; c1 = tc; }
        g_cB[t] = make_float2(c0, c1);
        int pr = 7 * j0 - (j0 * (j0 - 1)) / 2 + (j1 - j0 - 1);
        int pos = atomicAdd(&g_cnt[pr], 1);
        g_list[pr * T_MAX + pos] = t;
    }

    // deterministic block reduction of prob partials
    __shared__ float wred[8][16];
    int lane = threadIdx.x & 31, wid = threadIdx.x >> 5;
#pragma unroll
    for (int j = 0; j < 16; j++) {
        float v = (j < 8) ? pa[j] : pb[j - 8];
#pragma unroll
        for (int o = 16; o > 0; o >>= 1) v += __shfl_down_sync(0xffffffffu, v, o);
        if (lane == 0) wred[wid][j] = v;
    }
    __syncthreads();
    if (threadIdx.x < 16) {
        float acc = 0.f;
#pragma unroll
        for (int w = 0; w < 8; w++) acc += wred[w][threadIdx.x];
        g_part[bid * 16 + threadIdx.x] = acc;
    }
}

// -------- kernel 2: phase A — w via cp.async smem (2 buf), x via register-prefetched LDG --------
// grid (28 pairs, 16 tiles), 256 threads (8 warps x TW=4 tokens = 32 tokens/CTA).
// smem: 2 x 16KB weight buffers (8 pr x 256 col u64, swizzled).
__global__ __launch_bounds__(256, 2) void k_phaseA(const float* __restrict__ x) {
    int pair = blockIdx.x;
    int cnt = g_cntA[pair];

    int lo = 0, rem = pair;
#pragma unroll
    for (int l = 0; l < 7; l++) { int n = 7 - l; if (rem < n) { lo = l; break; } rem -= n; }
    int hi = lo + 1 + rem;
    int lo4 = lo * 4, hi4 = hi * 4;

    extern __shared__ __align__(16) char smc[];
    unsigned sbase = (unsigned)__cvta_generic_to_shared(smc);
    __shared__ int t_s[32];

    int tid = threadIdx.x, warp = tid >> 5, lane = tid & 31;

    // w staging tasks (4 float4 per thread per chunk): idx in [0,1024): pr=idx>>7, c16=idx&127
    unsigned wdst[4]; size_t wsrc[4];
#pragma unroll
    for (int k = 0; k < 4; k++) {
        int idx = k * 256 + tid;
        int pr = idx >> 7, c16 = idx & 127;
        int e4q = (pr < 4) ? (lo4 + pr) : (hi4 + pr - 4);
        wsrc[k] = (size_t)e4q * (DIN * 2) + c16 * 4;     // float offset; + ch*512
        wdst[k] = sw((unsigned)(pr * 2048 + c16 * 16));
    }

    for (int tbase = blockIdx.y * 32; tbase < cnt; tbase += 16 * 32) {
        __syncthreads();
        if (tid < 32) {
            int ti = tbase + tid;
            t_s[tid] = g_listA[pair * T_MAX + ((ti < cnt) ? ti : 0)];
        }
        __syncthreads();

        // per-token x base pointers (this thread covers cols lane*4 + it*128 + ch*256)
        const float* xp[TW];
#pragma unroll
        for (int j = 0; j < TW; j++)
            xp[j] = x + (size_t)t_s[warp * TW + j] * DIN + lane * 4;

        int tokv = tbase + warp * TW;

        uint64_t acc[TW][8];
#pragma unroll
        for (int j = 0; j < TW; j++)
#pragma unroll
            for (int p = 0; p < 8; p++) acc[j][p] = 0ull;

        // prologue: stage w chunk 0; prefetch x it0 of chunk 0
#pragma unroll
        for (int k = 0; k < 4; k++)
            cpasync16(sbase + wdst[k], g_wa2 + wsrc[k]);
        cpcommit();
        float4 x0[TW];
#pragma unroll
        for (int j = 0; j < TW; j++) x0[j] = *(const float4*)(xp[j]);

        for (int ch = 0; ch < NCHA; ++ch) {
            cpwait0();
            __syncthreads();
            if (ch + 1 < NCHA) {
                unsigned nb = (unsigned)(((ch + 1) & 1) * WBUF);
#pragma unroll
                for (int k = 0; k < 4; k++)
                    cpasync16(sbase + nb + wdst[k], g_wa2 + wsrc[k] + (ch + 1) * 512);
                cpcommit();
            }
            unsigned bufb = (unsigned)((ch & 1) * WBUF);

            // issue x loads for it1 of this chunk now (consumed ~1K cyc later)
            float4 x1[TW];
#pragma unroll
            for (int j = 0; j < TW; j++)
                x1[j] = *(const float4*)(xp[j] + ch * ACH + 128);

            // ---- it0: compute from prefetched x0 ----
            {
                uint64_t dx[TW][4];
#pragma unroll
                for (int j = 0; j < TW; j++) {
                    dx[j][0] = dup2(x0[j].x); dx[j][1] = dup2(x0[j].y);
                    dx[j][2] = dup2(x0[j].z); dx[j][3] = dup2(x0[j].w);
                }
#pragma unroll
                for (int pr = 0; pr < 8; ++pr) {
                    unsigned o0 = (unsigned)(pr * 2048 + lane * 32);
                    unsigned sA = bufb + sw(o0), sB = bufb + sw(o0 + 16);
                    uint64_t w0, w1, w2, w3;
                    asm("ld.shared.v2.b64 {%0,%1},[%2];" : "=l"(w0), "=l"(w1) : "r"(sbase + sA));
                    asm("ld.shared.v2.b64 {%0,%1},[%2];" : "=l"(w2), "=l"(w3) : "r"(sbase + sB));
#pragma unroll
                    for (int j = 0; j < TW; j++) {
                        ffma2(acc[j][pr], w0, dx[j][0]);
                        ffma2(acc[j][pr], w1, dx[j][1]);
                        ffma2(acc[j][pr], w2, dx[j][2]);
                        ffma2(acc[j][pr], w3, dx[j][3]);
                    }
                }
            }

            // prefetch x it0 of next chunk (x0 regs free now)
            if (ch + 1 < NCHA) {
#pragma unroll
                for (int j = 0; j < TW; j++)
                    x0[j] = *(const float4*)(xp[j] + (ch + 1) * ACH);
            }

            // ---- it1: compute from x1 ----
            {
                uint64_t dx[TW][4];
#pragma unroll
                for (int j = 0; j < TW; j++) {
                    dx[j][0] = dup2(x1[j].x); dx[j][1] = dup2(x1[j].y);
                    dx[j][2] = dup2(x1[j].z); dx[j][3] = dup2(x1[j].w);
                }
#pragma unroll
                for (int pr = 0; pr < 8; ++pr) {
                    unsigned o0 = (unsigned)(pr * 2048 + 1024 + lane * 32);
                    unsigned sA = bufb + sw(o0), sB = bufb + sw(o0 + 16);
                    uint64_t w0, w1, w2, w3;
                    asm("ld.shared.v2.b64 {%0,%1},[%2];" : "=l"(w0), "=l"(w1) : "r"(sbase + sA));
                    asm("ld.shared.v2.b64 {%0,%1},[%2];" : "=l"(w2), "=l"(w3) : "r"(sbase + sB));
#pragma unroll
                    for (int j = 0; j < TW; j++) {
                        ffma2(acc[j][pr], w0, dx[j][0]);
                        ffma2(acc[j][pr], w1, dx[j][1]);
                        ffma2(acc[j][pr], w2, dx[j][2]);
                        ffma2(acc[j][pr], w3, dx[j][3]);
                    }
                }
            }
        }

        // per-token cross-lane reduce + dup'd smid write
#pragma unroll
        for (int j = 0; j < TW; j++) {
            if (tokv + j >= cnt) continue;      // warp-uniform
            float a[16];
#pragma unroll
            for (int p = 0; p < 8; p++) {
                float2 f = u2f(acc[j][p]);
                a[2 * p] = f.x; a[2 * p + 1] = f.y;
            }
#pragma unroll
            for (int o = 16; o > 0; o >>= 1)
#pragma unroll
                for (int i = 0; i < 16; i++) a[i] += __shfl_down_sync(0xffffffffu, a[i], o);
            if (lane == 0) {
                int t = t_s[warp * TW + j];
                float2 wA = g_wA[t], cB = g_cB[t];
                float mid[8];
#pragma unroll
                for (int i = 0; i < 8; i++) mid[i] = wA.x * a[i] + wA.y * a[8 + i];
                float* d = g_smid2 + (size_t)t * 32;
#pragma unroll
                for (int h = 0; h < 2; h++) {
                    float c = h ? cB.y : cB.x;
#pragma unroll
                    for (int rp = 0; rp < 4; rp++) {
                        float v0 = c * mid[2 * rp], v1 = c * mid[2 * rp + 1];
                        *(float4*)(d + h * 16 + rp * 4) = make_float4(v0, v0, v1, v1);
                    }
                }
            }
        }
    }
}

// -------- kernel 3: phase B — col-paired accumulators, transposed Wb, token-split x4 --------
// grid (28 pairs, 8 col-blocks of 512, 4 token-slices), 128 threads, thread = 4 cols.
__global__ __launch_bounds__(128) void k_phaseB(float* __restrict__ out) {
    int pair = blockIdx.x, cb = blockIdx.y, q = blockIdx.z;
    int tid = threadIdx.x;

    int lo = 0, rem = pair;
#pragma unroll
    for (int l = 0; l < 7; l++) { int n = 7 - l; if (rem < n) { lo = l; break; } rem -= n; }
    int hi = lo + 1 + rem;

    int count = g_cnt[pair];
    int tstart = (count * q) >> 2, tend = (count * (q + 1)) >> 2;
    const int* lst = g_list + pair * T_MAX;
    int o0 = cb * 512 + tid * 4;

    // weights: w01[r] = cols (o0, o0+1), w23[r] = cols (o0+2, o0+3); r 0..7 lo, 8..15 hi
    uint64_t w01[16], w23[16];
#pragma unroll
    for (int r = 0; r < 16; r++) {
        int e = (r < 8) ? lo : hi;
        float4 v = *(const float4*)(g_wb2 + (size_t)e * 32768 + (size_t)(r & 7) * 4096 + o0);
        w01[r] = pack2(v.x, v.y);
        w23[r] = pack2(v.z, v.w);
    }

    __shared__ __align__(16) float s_s[64 * 32];
    __shared__ int t_s[64];

    for (int base = tstart; base < tend; base += 64) {
        int n = min(64, tend - base);
        __syncthreads();
        if (tid < n) t_s[tid] = lst[base + tid];
        for (int v = tid; v < n * 8; v += 128) {
            int tk = v >> 3, part = v & 7;
            int t = lst[base + tk];
            *(float4*)(s_s + tk * 32 + part * 4) =
                *(const float4*)(g_smid2 + (size_t)t * 32 + part * 4);
        }
        __syncthreads();

        int i = 0;
        for (; i + 1 < n; i += 2) {
            const float* sp0 = s_s + i * 32;
            const float* sp1 = sp0 + 32;
            uint64_t aA0 = 0, aA1 = 0, aB0 = 0, aB1 = 0;
            uint64_t bA0 = 0, bA1 = 0, bB0 = 0, bB1 = 0;
#pragma unroll
            for (int r = 0; r < 16; r++) {
                uint64_t sv0 = *(const uint64_t*)(sp0 + 2 * r);
                uint64_t sv1 = *(const uint64_t*)(sp1 + 2 * r);
                if (r & 1) {
                    ffma2(aA1, sv0, w01[r]); ffma2(aB1, sv0, w23[r]);
                    ffma2(bA1, sv1, w01[r]); ffma2(bB1, sv1, w23[r]);
                } else {
                    ffma2(aA0, sv0, w01[r]); ffma2(aB0, sv0, w23[r]);
                    ffma2(bA0, sv1, w01[r]); ffma2(bB0, sv1, w23[r]);
                }
            }
            float2 fa = u2f(add2(aA0, aA1)), fb = u2f(add2(aB0, aB1));
            *(float4*)(out + (size_t)t_s[i] * DOUT + o0) = make_float4(fa.x, fa.y, fb.x, fb.y);
            float2 ga = u2f(add2(bA0, bA1)), gb = u2f(add2(bB0, bB1));
            *(float4*)(out + (size_t)t_s[i + 1] * DOUT + o0) = make_float4(ga.x, ga.y, gb.x, gb.y);
        }
        if (i < n) {
            const float* sp0 = s_s + i * 32;
            uint64_t aA0 = 0, aA1 = 0, aB0 = 0, aB1 = 0;
#pragma unroll
            for (int r = 0; r < 16; r++) {
                uint64_t sv0 = *(const uint64_t*)(sp0 + 2 * r);
                if (r & 1) { ffma2(aA1, sv0, w01[r]); ffma2(aB1, sv0, w23[r]); }
                else       { ffma2(aA0, sv0, w01[r]); ffma2(aB0, sv0, w23[r]); }
            }
            float2 fa = u2f(add2(aA0, aA1)), fb = u2f(add2(aB0, aB1));
            *(float4*)(out + (size_t)t_s[i] * DOUT + o0) = make_float4(fa.x, fa.y, fb.x, fb.y);
        }
    }
}

// -------- kernel 4: aux losses (parallel reduction) + counter reset --------
__global__ void k_aux(float* __restrict__ out2, int T, int nblk) {
    __shared__ float red[16][17];
    __shared__ float p[16];
    int j = threadIdx.x & 15, g = threadIdx.x >> 4;    // 16 groups x 16 cols
    float s = 0.f;
    for (int b = g; b < nblk; b += 16) s += g_part[b * 16 + j];
    red[g][j] = s;
    __syncthreads();
    if (threadIdx.x < 16) {
        float acc = 0.f;
#pragma unroll
        for (int gg = 0; gg < 16; gg++) acc += red[gg][threadIdx.x];
        p[threadIdx.x] = acc / (float)T;
    }
    __syncthreads();
    if (threadIdx.x == 0) {
        float m = 0.f;
#pragma unroll
        for (int i = 0; i < 8; i++) m += p[i];
        m *= 0.125f;
        float v = 0.f;
#pragma unroll
        for (int i = 0; i < 8; i++) { float d = p[i] - m; v += d * d; }
        out2[0] = 8.f * (v / 7.f);

        float m2 = 0.f;
#pragma unroll
        for (int i = 8; i < 16; i++) m2 += p[i];
        m2 *= 0.125f;
        float v2 = 0.f;
#pragma unroll
        for (int i = 8; i < 16; i++) { float d = p[i] - m2; v2 += d * d; }
        out2[1] = 8.f * (v2 / 7.f);
    }
    // reset pair counters for the next graph replay (initial state is static zero)
    if (threadIdx.x < NPAIR) { g_cnt[threadIdx.x] = 0; g_cntA[threadIdx.x] = 0; }
}

// -------- launcher --------
extern "C" void kernel_launch(void* const* d_in, const int* in_sizes, int n_in,
                              void* d_out, int out_size) {
    const float* x  = (const float*)d_in[0];
    const float* la = (const float*)d_in[1];
    const float* lb = (const float*)d_in[2];
    const float* Wa = (const float*)d_in[3];
    const float* Wb = (const float*)d_in[4];
    float* out = (float*)d_out;

    int T = in_sizes[1] / NE;           // 8192
    if (T > T_MAX) return;
    int nblk = (T + 255) / 256;

    static int smem_set = 0;
    int smemA = 2 * WBUF;               // 32 KB
    if (!smem_set) {
        cudaFuncSetAttribute(k_phaseA, cudaFuncAttributeMaxDynamicSharedMemorySize, smemA);
        smem_set = 1;
    }

    k_prep_route<<<384 + nblk, 256>>>(Wa, Wb, la, lb, T);
    dim3 gA(NPAIR, 16);
    k_phaseA<<<gA, 256, smemA>>>(x);
    dim3 gB(NPAIR, DOUT / 512, 4);
    k_phaseB<<<gB, 128>>>(out);
    k_aux<<<1, 256>>>(out + (size_t)out_size - 2, T, nblk);
}

// round 16
// speedup vs baseline: 1.2818x; 1.0007x over previous
#include <cuda_runtime.h>
#include <cstdint>

#define T_MAX   8192
#define DIN     4096
#define DOUT    4096
#define NE      8
#define NPAIR   28
#define SCALING 2.0f            // 16.0 / r with r=8
#define TW      4               // tokens per warp in phase A
#define ACH     256             // phase A cols per chunk
#define NCHA    (DIN / ACH)     // 16 chunks
#define WBUF    16384           // per-buffer bytes: w only (8 pr x 256 col u64)

// -------- scratch (device globals; no allocations allowed) --------
__device__ int    g_cnt[NPAIR];                 // B-pair counts
__device__ int    g_list[NPAIR * T_MAX];        // B-pair token lists
__device__ int    g_cntA[NPAIR];                // A-pair counts
__device__ int    g_listA[NPAIR * T_MAX];       // A-pair token lists
__device__ float2 g_wA[T_MAX];                  // A weights, sorted (lo, hi)
__device__ float2 g_cB[T_MAX];                  // B coeffs (incl. SCALING), sorted
__device__ __align__(16) float g_smid2[T_MAX * 32];   // dup'd scaled s: (v,v) pairs
__device__ float  g_part[64 * 16];
// paired Wa: g_wa2[(e*4+q)*4096 + c] as u64 = (Wa[e][2q][c], Wa[e][2q+1][c])
__device__ __align__(16) float g_wa2[NE * 4 * DIN * 2];
// transposed Wb: g_wb2[e][r][col]
__device__ __align__(16) float g_wb2[NE * 8 * DOUT];

// -------- helpers --------
__device__ __forceinline__ void ffma2(uint64_t& acc, uint64_t a, uint64_t b) {
    asm("fma.rn.f32x2 %0, %1, %2, %0;" : "+l"(acc) : "l"(a), "l"(b));
}
__device__ __forceinline__ uint64_t add2(uint64_t a, uint64_t b) {
    uint64_t r;
    asm("add.rn.f32x2 %0, %1, %2;" : "=l"(r) : "l"(a), "l"(b));
    return r;
}
__device__ __forceinline__ float2 u2f(uint64_t v) {
    float2 f;
    f.x = __uint_as_float((unsigned)(v & 0xffffffffu));
    f.y = __uint_as_float((unsigned)(v >> 32));
    return f;
}
__device__ __forceinline__ uint64_t dup2(float v) {
    uint64_t r; unsigned u = __float_as_uint(v);
    asm("mov.b64 %0, {%1, %2};" : "=l"(r) : "r"(u), "r"(u));
    return r;
}
__device__ __forceinline__ uint64_t pack2(float a, float b) {
    uint64_t r;
    asm("mov.b64 %0, {%1, %2};" : "=l"(r) : "r"(__float_as_uint(a)), "r"(__float_as_uint(b)));
    return r;
}
__device__ __forceinline__ unsigned sw(unsigned off) { return off ^ ((off >> 3) & 0x70u); }
__device__ __forceinline__ void cpasync16(unsigned dst, const void* src) {
    asm volatile("cp.async.cg.shared.global [%0], [%1], 16;" :: "r"(dst), "l"(src) : "memory");
}
__device__ __forceinline__ void cpcommit() {
    asm volatile("cp.async.commit_group;" ::: "memory");
}
__device__ __forceinline__ void cpwait0() {
    asm volatile("cp.async.wait_group 0;" ::: "memory");
}

// -------- fused prep+route kernel --------
// blocks [0,128): paired Wa; [128,192): transposed Wb (smem tile transpose); [192,...): routing.
__device__ __forceinline__ void do_prepA(const float* __restrict__ Wa, int bid) {
    int idx = bid * 256 + threadIdx.x;             // 32768 tasks: e4q(32) x c4(1024)
    int e4q = idx >> 10, c4 = idx & 1023;
    int e = e4q >> 2, q = e4q & 3;
    float4 a = *(const float4*)(Wa + ((size_t)(e * 8 + 2 * q) * DIN + c4 * 4));
    float4 b = *(const float4*)(Wa + ((size_t)(e * 8 + 2 * q + 1) * DIN + c4 * 4));
    float* dst = g_wa2 + ((size_t)e4q * DIN + c4 * 4) * 2;
    *(float4*)(dst)     = make_float4(a.x, b.x, a.y, b.y);
    *(float4*)(dst + 4) = make_float4(a.z, b.z, a.w, b.w);
}

// coalesced Wb transpose via padded smem: block = (expert, 512-col slab)
__device__ __forceinline__ void do_prepB(const float* __restrict__ Wb, int bid,
                                         float* s_tr /* 512*9 floats */) {
    int e = bid >> 3, cb = bid & 7;
    int o0 = cb * 512;
    // read 512 rows x 8 r = 1024 float4, fully coalesced
#pragma unroll
    for (int it = 0; it < 4; ++it) {
        int idx = it * 256 + threadIdx.x;          // 0..1023
        int o = idx >> 1, half = idx & 1;
        float4 v = *(const float4*)(Wb + (size_t)e * 32768 + (size_t)(o0 + o) * 8 + half * 4);
        float* d = s_tr + o * 9 + half * 4;
        d[0] = v.x; d[1] = v.y; d[2] = v.z; d[3] = v.w;
    }
    __syncthreads();
    // write 8 r-rows x 512 cols = 1024 float4, fully coalesced
#pragma unroll
    for (int it = 0; it < 4; ++it) {
        int idx = it * 256 + threadIdx.x;          // 0..1023
        int r = idx >> 7, o4 = idx & 127;
        const float* s = s_tr + (o4 * 4) * 9 + r;
        float4 v = make_float4(s[0], s[9], s[18], s[27]);
        *(float4*)(g_wb2 + (size_t)e * 32768 + (size_t)r * 4096 + o0 + o4 * 4) = v;
    }
}

__global__ void k_prep_route(const float* __restrict__ Wa, const float* __restrict__ Wb,
                             const float* __restrict__ la, const float* __restrict__ lb, int T) {
    __shared__ float s_tr[512 * 9];
    if (blockIdx.x < 128) { do_prepA(Wa, blockIdx.x); return; }
    if (blockIdx.x < 192) { do_prepB(Wb, blockIdx.x - 128, s_tr); return; }
    int bid = blockIdx.x - 192;
    int t = bid * 256 + threadIdx.x;
    float pa[8], pb[8];
#pragma unroll
    for (int i = 0; i < 8; i++) { pa[i] = 0.f; pb[i] = 0.f; }

    if (t < T) {
        // ---- A router ----
        float l[8];
        float4 u0 = *(const float4*)(la + (size_t)t * 8);
        float4 u1 = *(const float4*)(la + (size_t)t * 8 + 4);
        l[0]=u0.x; l[1]=u0.y; l[2]=u0.z; l[3]=u0.w;
        l[4]=u1.x; l[5]=u1.y; l[6]=u1.z; l[7]=u1.w;
        int i0 = 0; float v0 = l[0];
#pragma unroll
        for (int i = 1; i < 8; i++) if (l[i] > v0) { v0 = l[i]; i0 = i; }
        int i1 = -1; float v1 = -1e30f;
#pragma unroll
        for (int i = 0; i < 8; i++) if (i != i0 && l[i] > v1) { v1 = l[i]; i1 = i; }
        float e1 = expf(v1 - v0);
        float inv01 = 1.f / (1.f + e1);
        float wa0 = inv01, wa1 = e1 * inv01;
        float s = 0.f;
#pragma unroll
        for (int i = 0; i < 8; i++) { pa[i] = expf(l[i] - v0); s += pa[i]; }
        float invs = 1.f / s;
#pragma unroll
        for (int i = 0; i < 8; i++) pa[i] *= invs;
        if (i0 > i1) { int ti = i0; i0 = i1; i1 = ti; float tw = wa0; wa0 = wa1; wa1 = tw; }
        g_wA[t] = make_float2(wa0, wa1);
        int prA = 7 * i0 - (i0 * (i0 - 1)) / 2 + (i1 - i0 - 1);
        int posA = atomicAdd(&g_cntA[prA], 1);
        g_listA[prA * T_MAX + posA] = t;

        // ---- B router ----
        float m[8];
        float4 b0 = *(const float4*)(lb + (size_t)t * 8);
        float4 b1 = *(const float4*)(lb + (size_t)t * 8 + 4);
        m[0]=b0.x; m[1]=b0.y; m[2]=b0.z; m[3]=b0.w;
        m[4]=b1.x; m[5]=b1.y; m[6]=b1.z; m[7]=b1.w;
        int j0 = 0; float w0 = m[0];
#pragma unroll
        for (int i = 1; i < 8; i++) if (m[i] > w0) { w0 = m[i]; j0 = i; }
        int j1 = -1; float w1 = -1e30f;
#pragma unroll
        for (int i = 0; i < 8; i++) if (i != j0 && m[i] > w1) { w1 = m[i]; j1 = i; }
        float eb = expf(w1 - w0);
        float invb = 1.f / (1.f + eb);
        float c0 = SCALING * invb;
        float c1 = SCALING * eb * invb;
        s = 0.f;
#pragma unroll
        for (int i = 0; i < 8; i++) { pb[i] = expf(m[i] - w0); s += pb[i]; }
        invs = 1.f / s;
#pragma unroll
        for (int i = 0; i < 8; i++) pb[i] *= invs;
        if (j0 > j1) { int tj = j0; j0 = j1; j1 = tj; float tc = c0; c0 = c1; c1 = tc; }
        g_cB[t] = make_float2(c0, c1);
        int pr = 7 * j0 - (j0 * (j0 - 1)) / 2 + (j1 - j0 - 1);
        int pos = atomicAdd(&g_cnt[pr], 1);
        g_list[pr * T_MAX + pos] = t;
    }

    // deterministic block reduction of prob partials
    __shared__ float wred[8][16];
    int lane = threadIdx.x & 31, wid = threadIdx.x >> 5;
#pragma unroll
    for (int j = 0; j < 16; j++) {
        float v = (j < 8) ? pa[j] : pb[j - 8];
#pragma unroll
        for (int o = 16; o > 0; o >>= 1) v += __shfl_down_sync(0xffffffffu, v, o);
        if (lane == 0) wred[wid][j] = v;
    }
    __syncthreads();
    if (threadIdx.x < 16) {
        float acc = 0.f;
#pragma unroll
        for (int w = 0; w < 8; w++) acc += wred[w][threadIdx.x];
        g_part[bid * 16 + threadIdx.x] = acc;
    }
}

// -------- kernel 2: phase A — w via cp.async smem (2 buf), x via register-prefetched LDG --------
// grid (28 pairs, 16 tiles), 256 threads (8 warps x TW=4 tokens = 32 tokens/CTA).
// smem: 2 x 16KB weight buffers (8 pr x 256 col u64, swizzled).
__global__ __launch_bounds__(256, 2) void k_phaseA(const float* __restrict__ x) {
    int pair = blockIdx.x;
    int cnt = g_cntA[pair];

    int lo = 0, rem = pair;
#pragma unroll
    for (int l = 0; l < 7; l++) { int n = 7 - l; if (rem < n) { lo = l; break; } rem -= n; }
    int hi = lo + 1 + rem;
    int lo4 = lo * 4, hi4 = hi * 4;

    extern __shared__ __align__(16) char smc[];
    unsigned sbase = (unsigned)__cvta_generic_to_shared(smc);
    __shared__ int t_s[32];

    int tid = threadIdx.x, warp = tid >> 5, lane = tid & 31;

    // w staging tasks (4 float4 per thread per chunk): idx in [0,1024): pr=idx>>7, c16=idx&127
    unsigned wdst[4]; size_t wsrc[4];
#pragma unroll
    for (int k = 0; k < 4; k++) {
        int idx = k * 256 + tid;
        int pr = idx >> 7, c16 = idx & 127;
        int e4q = (pr < 4) ? (lo4 + pr) : (hi4 + pr - 4);
        wsrc[k] = (size_t)e4q * (DIN * 2) + c16 * 4;     // float offset; + ch*512
        wdst[k] = sw((unsigned)(pr * 2048 + c16 * 16));
    }

    for (int tbase = blockIdx.y * 32; tbase < cnt; tbase += 16 * 32) {
        __syncthreads();
        if (tid < 32) {
            int ti = tbase + tid;
            t_s[tid] = g_listA[pair * T_MAX + ((ti < cnt) ? ti : 0)];
        }
        __syncthreads();

        // per-token x base pointers (this thread covers cols lane*4 + it*128 + ch*256)
        const float* xp[TW];
#pragma unroll
        for (int j = 0; j < TW; j++)
            xp[j] = x + (size_t)t_s[warp * TW + j] * DIN + lane * 4;

        int tokv = tbase + warp * TW;

        uint64_t acc[TW][8];
#pragma unroll
        for (int j = 0; j < TW; j++)
#pragma unroll
            for (int p = 0; p < 8; p++) acc[j][p] = 0ull;

        // prologue: stage w chunk 0; prefetch x it0 of chunk 0
#pragma unroll
        for (int k = 0; k < 4; k++)
            cpasync16(sbase + wdst[k], g_wa2 + wsrc[k]);
        cpcommit();
        float4 x0[TW];
#pragma unroll
        for (int j = 0; j < TW; j++) x0[j] = *(const float4*)(xp[j]);

        for (int ch = 0; ch < NCHA; ++ch) {
            cpwait0();
            __syncthreads();
            if (ch + 1 < NCHA) {
                unsigned nb = (unsigned)(((ch + 1) & 1) * WBUF);
#pragma unroll
                for (int k = 0; k < 4; k++)
                    cpasync16(sbase + nb + wdst[k], g_wa2 + wsrc[k] + (ch + 1) * 512);
                cpcommit();
            }
            unsigned bufb = (unsigned)((ch & 1) * WBUF);

            // issue x loads for it1 of this chunk now (consumed ~1K cyc later)
            float4 x1[TW];
#pragma unroll
            for (int j = 0; j < TW; j++)
                x1[j] = *(const float4*)(xp[j] + ch * ACH + 128);

            // ---- it0: compute from prefetched x0 ----
            {
                uint64_t dx[TW][4];
#pragma unroll
                for (int j = 0; j < TW; j++) {
                    dx[j][0] = dup2(x0[j].x); dx[j][1] = dup2(x0[j].y);
                    dx[j][2] = dup2(x0[j].z); dx[j][3] = dup2(x0[j].w);
                }
#pragma unroll
                for (int pr = 0; pr < 8; ++pr) {
                    unsigned o0 = (unsigned)(pr * 2048 + lane * 32);
                    unsigned sA = bufb + sw(o0), sB = bufb + sw(o0 + 16);
                    uint64_t w0, w1, w2, w3;
                    asm("ld.shared.v2.b64 {%0,%1},[%2];" : "=l"(w0), "=l"(w1) : "r"(sbase + sA));
                    asm("ld.shared.v2.b64 {%0,%1},[%2];" : "=l"(w2), "=l"(w3) : "r"(sbase + sB));
#pragma unroll
                    for (int j = 0; j < TW; j++) {
                        ffma2(acc[j][pr], w0, dx[j][0]);
                        ffma2(acc[j][pr], w1, dx[j][1]);
                        ffma2(acc[j][pr], w2, dx[j][2]);
                        ffma2(acc[j][pr], w3, dx[j][3]);
                    }
                }
            }

            // prefetch x it0 of next chunk (x0 regs free now)
            if (ch + 1 < NCHA) {
#pragma unroll
                for (int j = 0; j < TW; j++)
                    x0[j] = *(const float4*)(xp[j] + (ch + 1) * ACH);
            }

            // ---- it1: compute from x1 ----
            {
                uint64_t dx[TW][4];
#pragma unroll
                for (int j = 0; j < TW; j++) {
                    dx[j][0] = dup2(x1[j].x); dx[j][1] = dup2(x1[j].y);
                    dx[j][2] = dup2(x1[j].z); dx[j][3] = dup2(x1[j].w);
                }
#pragma unroll
                for (int pr = 0; pr < 8; ++pr) {
                    unsigned o0 = (unsigned)(pr * 2048 + 1024 + lane * 32);
                    unsigned sA = bufb + sw(o0), sB = bufb + sw(o0 + 16);
                    uint64_t w0, w1, w2, w3;
                    asm("ld.shared.v2.b64 {%0,%1},[%2];" : "=l"(w0), "=l"(w1) : "r"(sbase + sA));
                    asm("ld.shared.v2.b64 {%0,%1},[%2];" : "=l"(w2), "=l"(w3) : "r"(sbase + sB));
#pragma unroll
                    for (int j = 0; j < TW; j++) {
                        ffma2(acc[j][pr], w0, dx[j][0]);
                        ffma2(acc[j][pr], w1, dx[j][1]);
                        ffma2(acc[j][pr], w2, dx[j][2]);
                        ffma2(acc[j][pr], w3, dx[j][3]);
                    }
                }
            }
        }

        // per-token cross-lane reduce + dup'd smid write
#pragma unroll
        for (int j = 0; j < TW; j++) {
            if (tokv + j >= cnt) continue;      // warp-uniform
            float a[16];
#pragma unroll
            for (int p = 0; p < 8; p++) {
                float2 f = u2f(acc[j][p]);
                a[2 * p] = f.x; a[2 * p + 1] = f.y;
            }
#pragma unroll
            for (int o = 16; o > 0; o >>= 1)
#pragma unroll
                for (int i = 0; i < 16; i++) a[i] += __shfl_down_sync(0xffffffffu, a[i], o);
            if (lane == 0) {
                int t = t_s[warp * TW + j];
                float2 wA = g_wA[t], cB = g_cB[t];
                float mid[8];
#pragma unroll
                for (int i = 0; i < 8; i++) mid[i] = wA.x * a[i] + wA.y * a[8 + i];
                float* d = g_smid2 + (size_t)t * 32;
#pragma unroll
                for (int h = 0; h < 2; h++) {
                    float c = h ? cB.y : cB.x;
#pragma unroll
                    for (int rp = 0; rp < 4; rp++) {
                        float v0 = c * mid[2 * rp], v1 = c * mid[2 * rp + 1];
                        *(float4*)(d + h * 16 + rp * 4) = make_float4(v0, v0, v1, v1);
                    }
                }
            }
        }
    }
}

// -------- kernel 3: phase B — col-paired accumulators, transposed Wb, token-split x4 --------
// grid (28 pairs, 8 col-blocks of 512, 4 token-slices), 128 threads, thread = 4 cols.
__global__ __launch_bounds__(128) void k_phaseB(float* __restrict__ out) {
    int pair = blockIdx.x, cb = blockIdx.y, q = blockIdx.z;
    int tid = threadIdx.x;

    int lo = 0, rem = pair;
#pragma unroll
    for (int l = 0; l < 7; l++) { int n = 7 - l; if (rem < n) { lo = l; break; } rem -= n; }
    int hi = lo + 1 + rem;

    int count = g_cnt[pair];
    int tstart = (count * q) >> 2, tend = (count * (q + 1)) >> 2;
    const int* lst = g_list + pair * T_MAX;
    int o0 = cb * 512 + tid * 4;

    // weights: w01[r] = cols (o0, o0+1), w23[r] = cols (o0+2, o0+3); r 0..7 lo, 8..15 hi
    uint64_t w01[16], w23[16];
#pragma unroll
    for (int r = 0; r < 16; r++) {
        int e = (r < 8) ? lo : hi;
        float4 v = *(const float4*)(g_wb2 + (size_t)e * 32768 + (size_t)(r & 7) * 4096 + o0);
        w01[r] = pack2(v.x, v.y);
        w23[r] = pack2(v.z, v.w);
    }

    __shared__ __align__(16) float s_s[64 * 32];
    __shared__ int t_s[64];

    for (int base = tstart; base < tend; base += 64) {
        int n = min(64, tend - base);
        __syncthreads();
        if (tid < n) t_s[tid] = lst[base + tid];
        for (int v = tid; v < n * 8; v += 128) {
            int tk = v >> 3, part = v & 7;
            int t = lst[base + tk];
            *(float4*)(s_s + tk * 32 + part * 4) =
                *(const float4*)(g_smid2 + (size_t)t * 32 + part * 4);
        }
        __syncthreads();

        int i = 0;
        for (; i + 1 < n; i += 2) {
            const float* sp0 = s_s + i * 32;
            const float* sp1 = sp0 + 32;
            uint64_t aA0 = 0, aA1 = 0, aB0 = 0, aB1 = 0;
            uint64_t bA0 = 0, bA1 = 0, bB0 = 0, bB1 = 0;
#pragma unroll
            for (int r = 0; r < 16; r++) {
                uint64_t sv0 = *(const uint64_t*)(sp0 + 2 * r);
                uint64_t sv1 = *(const uint64_t*)(sp1 + 2 * r);
                if (r & 1) {
                    ffma2(aA1, sv0, w01[r]); ffma2(aB1, sv0, w23[r]);
                    ffma2(bA1, sv1, w01[r]); ffma2(bB1, sv1, w23[r]);
                } else {
                    ffma2(aA0, sv0, w01[r]); ffma2(aB0, sv0, w23[r]);
                    ffma2(bA0, sv1, w01[r]); ffma2(bB0, sv1, w23[r]);
                }
            }
            float2 fa = u2f(add2(aA0, aA1)), fb = u2f(add2(aB0, aB1));
            *(float4*)(out + (size_t)t_s[i] * DOUT + o0) = make_float4(fa.x, fa.y, fb.x, fb.y);
            float2 ga = u2f(add2(bA0, bA1)), gb = u2f(add2(bB0, bB1));
            *(float4*)(out + (size_t)t_s[i + 1] * DOUT + o0) = make_float4(ga.x, ga.y, gb.x, gb.y);
        }
        if (i < n) {
            const float* sp0 = s_s + i * 32;
            uint64_t aA0 = 0, aA1 = 0, aB0 = 0, aB1 = 0;
#pragma unroll
            for (int r = 0; r < 16; r++) {
                uint64_t sv0 = *(const uint64_t*)(sp0 + 2 * r);
                if (r & 1) { ffma2(aA1, sv0, w01[r]); ffma2(aB1, sv0, w23[r]); }
                else       { ffma2(aA0, sv0, w01[r]); ffma2(aB0, sv0, w23[r]); }
            }
            float2 fa = u2f(add2(aA0, aA1)), fb = u2f(add2(aB0, aB1));
            *(float4*)(out + (size_t)t_s[i] * DOUT + o0) = make_float4(fa.x, fa.y, fb.x, fb.y);
        }
    }
}

// -------- kernel 4: aux losses (parallel reduction) + counter reset --------
__global__ void k_aux(float* __restrict__ out2, int T, int nblk) {
    __shared__ float red[16][17];
    __shared__ float p[16];
    int j = threadIdx.x & 15, g = threadIdx.x >> 4;    // 16 groups x 16 cols
    float s = 0.f;
    for (int b = g; b < nblk; b += 16) s += g_part[b * 16 + j];
    red[g][j] = s;
    __syncthreads();
    if (threadIdx.x < 16) {
        float acc = 0.f;
#pragma unroll
        for (int gg = 0; gg < 16; gg++) acc += red[gg][threadIdx.x];
        p[threadIdx.x] = acc / (float)T;
    }
    __syncthreads();
    if (threadIdx.x == 0) {
        float m = 0.f;
#pragma unroll
        for (int i = 0; i < 8; i++) m += p[i];
        m *= 0.125f;
        float v = 0.f;
#pragma unroll
        for (int i = 0; i < 8; i++) { float d = p[i] - m; v += d * d; }
        out2[0] = 8.f * (v / 7.f);

        float m2 = 0.f;
#pragma unroll
        for (int i = 8; i < 16; i++) m2 += p[i];
        m2 *= 0.125f;
        float v2 = 0.f;
#pragma unroll
        for (int i = 8; i < 16; i++) { float d = p[i] - m2; v2 += d * d; }
        out2[1] = 8.f * (v2 / 7.f);
    }
    // reset pair counters for the next graph replay (initial state is static zero)
    if (threadIdx.x < NPAIR) { g_cnt[threadIdx.x] = 0; g_cntA[threadIdx.x] = 0; }
}

// -------- launcher --------
extern "C" void kernel_launch(void* const* d_in, const int* in_sizes, int n_in,
                              void* d_out, int out_size) {
    const float* x  = (const float*)d_in[0];
    const float* la = (const float*)d_in[1];
    const float* lb = (const float*)d_in[2];
    const float* Wa = (const float*)d_in[3];
    const float* Wb = (const float*)d_in[4];
    float* out = (float*)d_out;

    int T = in_sizes[1] / NE;           // 8192
    if (T > T_MAX) return;
    int nblk = (T + 255) / 256;

    static int smem_set = 0;
    int smemA = 2 * WBUF;               // 32 KB
    if (!smem_set) {
        cudaFuncSetAttribute(k_phaseA, cudaFuncAttributeMaxDynamicSharedMemorySize, smemA);
        smem_set = 1;
    }

    k_prep_route<<<192 + nblk, 256>>>(Wa, Wb, la, lb, T);
    dim3 gA(NPAIR, 16);
    k_phaseA<<<gA, 256, smemA>>>(x);
    dim3 gB(NPAIR, DOUT / 512, 4);
    k_phaseB<<<gB, 128>>>(out);
    k_aux<<<1, 256>>>(out + (size_t)out_size - 2, T, nblk);
}

// round 17
// speedup vs baseline: 1.3016x; 1.0155x over previous
#include <cuda_runtime.h>
#include <cstdint>

#define T_MAX   8192
#define DIN     4096
#define DOUT    4096
#define NE      8
#define NPAIR   28
#define SCALING 2.0f            // 16.0 / r with r=8
#define TW      4               // tokens per warp in phase A
#define ACH     256             // phase A cols per chunk
#define NCHA    (DIN / ACH)     // 16 chunks
#define WBUF    16384           // per-buffer bytes: w only (8 pr x 256 col u64)

// -------- scratch (device globals; no allocations allowed) --------
__device__ int    g_cnt[NPAIR];                 // B-pair counts
__device__ int    g_list[NPAIR * T_MAX];        // B-pair token lists
__device__ int    g_cntA[NPAIR];                // A-pair counts
__device__ int    g_listA[NPAIR * T_MAX];       // A-pair token lists
__device__ float2 g_wA[T_MAX];                  // A weights, sorted (lo, hi)
__device__ float2 g_cB[T_MAX];                  // B coeffs (incl. SCALING), sorted
__device__ __align__(16) float g_smid2[T_MAX * 32];   // dup'd scaled s: (v,v) pairs
__device__ float  g_part[64 * 16];
// paired Wa: g_wa2[(e*4+q)*4096 + c] as u64 = (Wa[e][2q][c], Wa[e][2q+1][c])
__device__ __align__(16) float g_wa2[NE * 4 * DIN * 2];
// transposed Wb: g_wb2[e][r][col]
__device__ __align__(16) float g_wb2[NE * 8 * DOUT];

// -------- helpers --------
__device__ __forceinline__ void ffma2(uint64_t& acc, uint64_t a, uint64_t b) {
    asm("fma.rn.f32x2 %0, %1, %2, %0;" : "+l"(acc) : "l"(a), "l"(b));
}
__device__ __forceinline__ uint64_t add2(uint64_t a, uint64_t b) {
    uint64_t r;
    asm("add.rn.f32x2 %0, %1, %2;" : "=l"(r) : "l"(a), "l"(b));
    return r;
}
__device__ __forceinline__ float2 u2f(uint64_t v) {
    float2 f;
    f.x = __uint_as_float((unsigned)(v & 0xffffffffu));
    f.y = __uint_as_float((unsigned)(v >> 32));
    return f;
}
__device__ __forceinline__ uint64_t dup2(float v) {
    uint64_t r; unsigned u = __float_as_uint(v);
    asm("mov.b64 %0, {%1, %2};" : "=l"(r) : "r"(u), "r"(u));
    return r;
}
__device__ __forceinline__ uint64_t pack2(float a, float b) {
    uint64_t r;
    asm("mov.b64 %0, {%1, %2};" : "=l"(r) : "r"(__float_as_uint(a)), "r"(__float_as_uint(b)));
    return r;
}
__device__ __forceinline__ unsigned sw(unsigned off) { return off ^ ((off >> 3) & 0x70u); }
__device__ __forceinline__ void cpasync16(unsigned dst, const void* src) {
    asm volatile("cp.async.cg.shared.global [%0], [%1], 16;" :: "r"(dst), "l"(src) : "memory");
}
__device__ __forceinline__ void cpcommit() {
    asm volatile("cp.async.commit_group;" ::: "memory");
}
__device__ __forceinline__ void cpwait0() {
    asm volatile("cp.async.wait_group 0;" ::: "memory");
}
__device__ __forceinline__ void grid_dep_sync() {
    asm volatile("griddepcontrol.wait;" ::: "memory");
}

// -------- fused prep+route kernel --------
// blocks [0,128): paired Wa; [128,192): transposed Wb (smem tile transpose); [192,...): routing.
__device__ __forceinline__ void do_prepA(const float* __restrict__ Wa, int bid) {
    int idx = bid * 256 + threadIdx.x;             // 32768 tasks: e4q(32) x c4(1024)
    int e4q = idx >> 10, c4 = idx & 1023;
    int e = e4q >> 2, q = e4q & 3;
    float4 a = *(const float4*)(Wa + ((size_t)(e * 8 + 2 * q) * DIN + c4 * 4));
    float4 b = *(const float4*)(Wa + ((size_t)(e * 8 + 2 * q + 1) * DIN + c4 * 4));
    float* dst = g_wa2 + ((size_t)e4q * DIN + c4 * 4) * 2;
    *(float4*)(dst)     = make_float4(a.x, b.x, a.y, b.y);
    *(float4*)(dst + 4) = make_float4(a.z, b.z, a.w, b.w);
}

// coalesced Wb transpose via padded smem: block = (expert, 512-col slab)
__device__ __forceinline__ void do_prepB(const float* __restrict__ Wb, int bid,
                                         float* s_tr /* 512*9 floats */) {
    int e = bid >> 3, cb = bid & 7;
    int o0 = cb * 512;
#pragma unroll
    for (int it = 0; it < 4; ++it) {
        int idx = it * 256 + threadIdx.x;          // 0..1023
        int o = idx >> 1, half = idx & 1;
        float4 v = *(const float4*)(Wb + (size_t)e * 32768 + (size_t)(o0 + o) * 8 + half * 4);
        float* d = s_tr + o * 9 + half * 4;
        d[0] = v.x; d[1] = v.y; d[2] = v.z; d[3] = v.w;
    }
    __syncthreads();
#pragma unroll
    for (int it = 0; it < 4; ++it) {
        int idx = it * 256 + threadIdx.x;          // 0..1023
        int r = idx >> 7, o4 = idx & 127;
        const float* s = s_tr + (o4 * 4) * 9 + r;
        float4 v = make_float4(s[0], s[9], s[18], s[27]);
        *(float4*)(g_wb2 + (size_t)e * 32768 + (size_t)r * 4096 + o0 + o4 * 4) = v;
    }
}

__global__ void k_prep_route(const float* __restrict__ Wa, const float* __restrict__ Wb,
                             const float* __restrict__ la, const float* __restrict__ lb, int T) {
    __shared__ float s_tr[512 * 9];
    if (blockIdx.x < 128) { do_prepA(Wa, blockIdx.x); return; }
    if (blockIdx.x < 192) { do_prepB(Wb, blockIdx.x - 128, s_tr); return; }
    int bid = blockIdx.x - 192;
    int t = bid * 256 + threadIdx.x;
    float pa[8], pb[8];
#pragma unroll
    for (int i = 0; i < 8; i++) { pa[i] = 0.f; pb[i] = 0.f; }

    if (t < T) {
        // ---- A router ----
        float l[8];
        float4 u0 = *(const float4*)(la + (size_t)t * 8);
        float4 u1 = *(const float4*)(la + (size_t)t * 8 + 4);
        l[0]=u0.x; l[1]=u0.y; l[2]=u0.z; l[3]=u0.w;
        l[4]=u1.x; l[5]=u1.y; l[6]=u1.z; l[7]=u1.w;
        int i0 = 0; float v0 = l[0];
#pragma unroll
        for (int i = 1; i < 8; i++) if (l[i] > v0) { v0 = l[i]; i0 = i; }
        int i1 = -1; float v1 = -1e30f;
#pragma unroll
        for (int i = 0; i < 8; i++) if (i != i0 && l[i] > v1) { v1 = l[i]; i1 = i; }
        float e1 = expf(v1 - v0);
        float inv01 = 1.f / (1.f + e1);
        float wa0 = inv01, wa1 = e1 * inv01;
        float s = 0.f;
#pragma unroll
        for (int i = 0; i < 8; i++) { pa[i] = expf(l[i] - v0); s += pa[i]; }
        float invs = 1.f / s;
#pragma unroll
        for (int i = 0; i < 8; i++) pa[i] *= invs;
        if (i0 > i1) { int ti = i0; i0 = i1; i1 = ti; float tw = wa0; wa0 = wa1; wa1 = tw; }
        g_wA[t] = make_float2(wa0, wa1);
        int prA = 7 * i0 - (i0 * (i0 - 1)) / 2 + (i1 - i0 - 1);
        int posA = atomicAdd(&g_cntA[prA], 1);
        g_listA[prA * T_MAX + posA] = t;

        // ---- B router ----
        float m[8];
        float4 b0 = *(const float4*)(lb + (size_t)t * 8);
        float4 b1 = *(const float4*)(lb + (size_t)t * 8 + 4);
        m[0]=b0.x; m[1]=b0.y; m[2]=b0.z; m[3]=b0.w;
        m[4]=b1.x; m[5]=b1.y; m[6]=b1.z; m[7]=b1.w;
        int j0 = 0; float w0 = m[0];
#pragma unroll
        for (int i = 1; i < 8; i++) if (m[i] > w0) { w0 = m[i]; j0 = i; }
        int j1 = -1; float w1 = -1e30f;
#pragma unroll
        for (int i = 0; i < 8; i++) if (i != j0 && m[i] > w1) { w1 = m[i]; j1 = i; }
        float eb = expf(w1 - w0);
        float invb = 1.f / (1.f + eb);
        float c0 = SCALING * invb;
        float c1 = SCALING * eb * invb;
        s = 0.f;
#pragma unroll
        for (int i = 0; i < 8; i++) { pb[i] = expf(m[i] - w0); s += pb[i]; }
        invs = 1.f / s;
#pragma unroll
        for (int i = 0; i < 8; i++) pb[i] *= invs;
        if (j0 > j1) { int tj = j0; j0 = j1; j1 = tj; float tc = c0; c0 = c1; c1 = tc; }
        g_cB[t] = make_float2(c0, c1);
        int pr = 7 * j0 - (j0 * (j0 - 1)) / 2 + (j1 - j0 - 1);
        int pos = atomicAdd(&g_cnt[pr], 1);
        g_list[pr * T_MAX + pos] = t;
    }

    // deterministic block reduction of prob partials
    __shared__ float wred[8][16];
    int lane = threadIdx.x & 31, wid = threadIdx.x >> 5;
#pragma unroll
    for (int j = 0; j < 16; j++) {
        float v = (j < 8) ? pa[j] : pb[j - 8];
#pragma unroll
        for (int o = 16; o > 0; o >>= 1) v += __shfl_down_sync(0xffffffffu, v, o);
        if (lane == 0) wred[wid][j] = v;
    }
    __syncthreads();
    if (threadIdx.x < 16) {
        float acc = 0.f;
#pragma unroll
        for (int w = 0; w < 8; w++) acc += wred[w][threadIdx.x];
        g_part[bid * 16 + threadIdx.x] = acc;
    }
}

// -------- kernel 2: phase A — PDL: geometry pre-sync, then wait on prep_route --------
// grid (28 pairs, 16 tiles), 256 threads (8 warps x TW=4 tokens = 32 tokens/CTA).
__global__ __launch_bounds__(256, 2) void k_phaseA(const float* __restrict__ x) {
    int pair = blockIdx.x;

    int lo = 0, rem = pair;
#pragma unroll
    for (int l = 0; l < 7; l++) { int n = 7 - l; if (rem < n) { lo = l; break; } rem -= n; }
    int hi = lo + 1 + rem;
    int lo4 = lo * 4, hi4 = hi * 4;

    extern __shared__ __align__(16) char smc[];
    unsigned sbase = (unsigned)__cvta_generic_to_shared(smc);
    __shared__ int t_s[32];

    int tid = threadIdx.x, warp = tid >> 5, lane = tid & 31;

    // pre-sync: staging geometry (pure arithmetic)
    unsigned wdst[4]; size_t wsrc[4];
#pragma unroll
    for (int k = 0; k < 4; k++) {
        int idx = k * 256 + tid;
        int pr = idx >> 7, c16 = idx & 127;
        int e4q = (pr < 4) ? (lo4 + pr) : (hi4 + pr - 4);
        wsrc[k] = (size_t)e4q * (DIN * 2) + c16 * 4;     // float offset; + ch*512
        wdst[k] = sw((unsigned)(pr * 2048 + c16 * 16));
    }

    grid_dep_sync();                     // wait for prep_route
    int cnt = g_cntA[pair];

    for (int tbase = blockIdx.y * 32; tbase < cnt; tbase += 16 * 32) {
        __syncthreads();
        if (tid < 32) {
            int ti = tbase + tid;
            t_s[tid] = g_listA[pair * T_MAX + ((ti < cnt) ? ti : 0)];
        }
        __syncthreads();

        const float* xp[TW];
#pragma unroll
        for (int j = 0; j < TW; j++)
            xp[j] = x + (size_t)t_s[warp * TW + j] * DIN + lane * 4;

        int tokv = tbase + warp * TW;

        uint64_t acc[TW][8];
#pragma unroll
        for (int j = 0; j < TW; j++)
#pragma unroll
            for (int p = 0; p < 8; p++) acc[j][p] = 0ull;

        // prologue: stage w chunk 0; prefetch x it0 of chunk 0
#pragma unroll
        for (int k = 0; k < 4; k++)
            cpasync16(sbase + wdst[k], g_wa2 + wsrc[k]);
        cpcommit();
        float4 x0[TW];
#pragma unroll
        for (int j = 0; j < TW; j++) x0[j] = *(const float4*)(xp[j]);

        for (int ch = 0; ch < NCHA; ++ch) {
            cpwait0();
            __syncthreads();
            if (ch + 1 < NCHA) {
                unsigned nb = (unsigned)(((ch + 1) & 1) * WBUF);
#pragma unroll
                for (int k = 0; k < 4; k++)
                    cpasync16(sbase + nb + wdst[k], g_wa2 + wsrc[k] + (ch + 1) * 512);
                cpcommit();
            }
            unsigned bufb = (unsigned)((ch & 1) * WBUF);

            // issue x loads for it1 of this chunk now (consumed ~1K cyc later)
            float4 x1[TW];
#pragma unroll
            for (int j = 0; j < TW; j++)
                x1[j] = *(const float4*)(xp[j] + ch * ACH + 128);

            // ---- it0 ----
            {
                uint64_t dx[TW][4];
#pragma unroll
                for (int j = 0; j < TW; j++) {
                    dx[j][0] = dup2(x0[j].x); dx[j][1] = dup2(x0[j].y);
                    dx[j][2] = dup2(x0[j].z); dx[j][3] = dup2(x0[j].w);
                }
#pragma unroll
                for (int pr = 0; pr < 8; ++pr) {
                    unsigned o0 = (unsigned)(pr * 2048 + lane * 32);
                    unsigned sA = bufb + sw(o0), sB = bufb + sw(o0 + 16);
                    uint64_t w0, w1, w2, w3;
                    asm("ld.shared.v2.b64 {%0,%1},[%2];" : "=l"(w0), "=l"(w1) : "r"(sbase + sA));
                    asm("ld.shared.v2.b64 {%0,%1},[%2];" : "=l"(w2), "=l"(w3) : "r"(sbase + sB));
#pragma unroll
                    for (int j = 0; j < TW; j++) {
                        ffma2(acc[j][pr], w0, dx[j][0]);
                        ffma2(acc[j][pr], w1, dx[j][1]);
                        ffma2(acc[j][pr], w2, dx[j][2]);
                        ffma2(acc[j][pr], w3, dx[j][3]);
                    }
                }
            }

            // prefetch x it0 of next chunk
            if (ch + 1 < NCHA) {
#pragma unroll
                for (int j = 0; j < TW; j++)
                    x0[j] = *(const float4*)(xp[j] + (ch + 1) * ACH);
            }

            // ---- it1 ----
            {
                uint64_t dx[TW][4];
#pragma unroll
                for (int j = 0; j < TW; j++) {
                    dx[j][0] = dup2(x1[j].x); dx[j][1] = dup2(x1[j].y);
                    dx[j][2] = dup2(x1[j].z); dx[j][3] = dup2(x1[j].w);
                }
#pragma unroll
                for (int pr = 0; pr < 8; ++pr) {
                    unsigned o0 = (unsigned)(pr * 2048 + 1024 + lane * 32);
                    unsigned sA = bufb + sw(o0), sB = bufb + sw(o0 + 16);
                    uint64_t w0, w1, w2, w3;
                    asm("ld.shared.v2.b64 {%0,%1},[%2];" : "=l"(w0), "=l"(w1) : "r"(sbase + sA));
                    asm("ld.shared.v2.b64 {%0,%1},[%2];" : "=l"(w2), "=l"(w3) : "r"(sbase + sB));
#pragma unroll
                    for (int j = 0; j < TW; j++) {
                        ffma2(acc[j][pr], w0, dx[j][0]);
                        ffma2(acc[j][pr], w1, dx[j][1]);
                        ffma2(acc[j][pr], w2, dx[j][2]);
                        ffma2(acc[j][pr], w3, dx[j][3]);
                    }
                }
            }
        }

        // per-token cross-lane reduce + dup'd smid write
#pragma unroll
        for (int j = 0; j < TW; j++) {
            if (tokv + j >= cnt) continue;      // warp-uniform
            float a[16];
#pragma unroll
            for (int p = 0; p < 8; p++) {
                float2 f = u2f(acc[j][p]);
                a[2 * p] = f.x; a[2 * p + 1] = f.y;
            }
#pragma unroll
            for (int o = 16; o > 0; o >>= 1)
#pragma unroll
                for (int i = 0; i < 16; i++) a[i] += __shfl_down_sync(0xffffffffu, a[i], o);
            if (lane == 0) {
                int t = t_s[warp * TW + j];
                float2 wA = g_wA[t], cB = g_cB[t];
                float mid[8];
#pragma unroll
                for (int i = 0; i < 8; i++) mid[i] = wA.x * a[i] + wA.y * a[8 + i];
                float* d = g_smid2 + (size_t)t * 32;
#pragma unroll
                for (int h = 0; h < 2; h++) {
                    float c = h ? cB.y : cB.x;
#pragma unroll
                    for (int rp = 0; rp < 4; rp++) {
                        float v0 = c * mid[2 * rp], v1 = c * mid[2 * rp + 1];
                        *(float4*)(d + h * 16 + rp * 4) = make_float4(v0, v0, v1, v1);
                    }
                }
            }
        }
    }
}

// -------- kernel 3: phase B — PDL: counts/list/weights pre-sync, wait before smid reads --------
// grid (28 pairs, 8 col-blocks of 512, 4 token-slices), 128 threads, thread = 4 cols.
__global__ __launch_bounds__(128) void k_phaseB(float* __restrict__ out) {
    int pair = blockIdx.x, cb = blockIdx.y, q = blockIdx.z;
    int tid = threadIdx.x;

    int lo = 0, rem = pair;
#pragma unroll
    for (int l = 0; l < 7; l++) { int n = 7 - l; if (rem < n) { lo = l; break; } rem -= n; }
    int hi = lo + 1 + rem;

    // pre-sync: counts/list pointer (prep_route data) + weight loads (g_wb2, prep_route)
    int count = g_cnt[pair];
    int tstart = (count * q) >> 2, tend = (count * (q + 1)) >> 2;
    const int* lst = g_list + pair * T_MAX;
    int o0 = cb * 512 + tid * 4;

    uint64_t w01[16], w23[16];
#pragma unroll
    for (int r = 0; r < 16; r++) {
        int e = (r < 8) ? lo : hi;
        float4 v = *(const float4*)(g_wb2 + (size_t)e * 32768 + (size_t)(r & 7) * 4096 + o0);
        w01[r] = pack2(v.x, v.y);
        w23[r] = pack2(v.z, v.w);
    }

    __shared__ __align__(16) float s_s[64 * 32];
    __shared__ int t_s[64];

    grid_dep_sync();                     // wait for phase A's g_smid2

    for (int base = tstart; base < tend; base += 64) {
        int n = min(64, tend - base);
        __syncthreads();
        if (tid < n) t_s[tid] = lst[base + tid];
        for (int v = tid; v < n * 8; v += 128) {
            int tk = v >> 3, part = v & 7;
            int t = lst[base + tk];
            *(float4*)(s_s + tk * 32 + part * 4) =
                *(const float4*)(g_smid2 + (size_t)t * 32 + part * 4);
        }
        __syncthreads();

        int i = 0;
        for (; i + 1 < n; i += 2) {
            const float* sp0 = s_s + i * 32;
            const float* sp1 = sp0 + 32;
            uint64_t aA0 = 0, aA1 = 0, aB0 = 0, aB1 = 0;
            uint64_t bA0 = 0, bA1 = 0, bB0 = 0, bB1 = 0;
#pragma unroll
            for (int r = 0; r < 16; r++) {
                uint64_t sv0 = *(const uint64_t*)(sp0 + 2 * r);
                uint64_t sv1 = *(const uint64_t*)(sp1 + 2 * r);
                if (r & 1) {
                    ffma2(aA1, sv0, w01[r]); ffma2(aB1, sv0, w23[r]);
                    ffma2(bA1, sv1, w01[r]); ffma2(bB1, sv1, w23[r]);
                } else {
                    ffma2(aA0, sv0, w01[r]); ffma2(aB0, sv0, w23[r]);
                    ffma2(bA0, sv1, w01[r]); ffma2(bB0, sv1, w23[r]);
                }
            }
            float2 fa = u2f(add2(aA0, aA1)), fb = u2f(add2(aB0, aB1));
            *(float4*)(out + (size_t)t_s[i] * DOUT + o0) = make_float4(fa.x, fa.y, fb.x, fb.y);
            float2 ga = u2f(add2(bA0, bA1)), gb = u2f(add2(bB0, bB1));
            *(float4*)(out + (size_t)t_s[i + 1] * DOUT + o0) = make_float4(ga.x, ga.y, gb.x, gb.y);
        }
        if (i < n) {
            const float* sp0 = s_s + i * 32;
            uint64_t aA0 = 0, aA1 = 0, aB0 = 0, aB1 = 0;
#pragma unroll
            for (int r = 0; r < 16; r++) {
                uint64_t sv0 = *(const uint64_t*)(sp0 + 2 * r);
                if (r & 1) { ffma2(aA1, sv0, w01[r]); ffma2(aB1, sv0, w23[r]); }
                else       { ffma2(aA0, sv0, w01[r]); ffma2(aB0, sv0, w23[r]); }
            }
            float2 fa = u2f(add2(aA0, aA1)), fb = u2f(add2(aB0, aB1));
            *(float4*)(out + (size_t)t_s[i] * DOUT + o0) = make_float4(fa.x, fa.y, fb.x, fb.y);
        }
    }
}

// -------- kernel 4: aux losses — PDL: reduction pre-sync; counter reset post-sync --------
__global__ void k_aux(float* __restrict__ out2, int T, int nblk) {
    __shared__ float red[16][17];
    __shared__ float p[16];
    int j = threadIdx.x & 15, g = threadIdx.x >> 4;    // 16 groups x 16 cols
    float s = 0.f;
    for (int b = g; b < nblk; b += 16) s += g_part[b * 16 + j];   // prep_route data
    red[g][j] = s;
    __syncthreads();
    if (threadIdx.x < 16) {
        float acc = 0.f;
#pragma unroll
        for (int gg = 0; gg < 16; gg++) acc += red[gg][threadIdx.x];
        p[threadIdx.x] = acc / (float)T;
    }
    __syncthreads();
    if (threadIdx.x == 0) {
        float m = 0.f;
#pragma unroll
        for (int i = 0; i < 8; i++) m += p[i];
        m *= 0.125f;
        float v = 0.f;
#pragma unroll
        for (int i = 0; i < 8; i++) { float d = p[i] - m; v += d * d; }
        out2[0] = 8.f * (v / 7.f);

        float m2 = 0.f;
#pragma unroll
        for (int i = 8; i < 16; i++) m2 += p[i];
        m2 *= 0.125f;
        float v2 = 0.f;
#pragma unroll
        for (int i = 8; i < 16; i++) { float d = p[i] - m2; v2 += d * d; }
        out2[1] = 8.f * (v2 / 7.f);
    }
    grid_dep_sync();                     // phase B must finish reading counters first
    if (threadIdx.x < NPAIR) { g_cnt[threadIdx.x] = 0; g_cntA[threadIdx.x] = 0; }
}

// -------- launcher --------
template <typename... Args>
static void launch_pdl(void (*kern)(Args...), dim3 grid, dim3 block, size_t smem,
                       Args... args) {
    cudaLaunchConfig_t cfg = {};
    cfg.gridDim = grid; cfg.blockDim = block;
    cfg.dynamicSmemBytes = smem; cfg.stream = 0;
    cudaLaunchAttribute at;
    at.id = cudaLaunchAttributeProgrammaticStreamSerialization;
    at.val.programmaticStreamSerializationAllowed = 1;
    cfg.attrs = &at; cfg.numAttrs = 1;
    cudaLaunchKernelEx(&cfg, kern, args...);
}

extern "C" void kernel_launch(void* const* d_in, const int* in_sizes, int n_in,
                              void* d_out, int out_size) {
    const float* x  = (const float*)d_in[0];
    const float* la = (const float*)d_in[1];
    const float* lb = (const float*)d_in[2];
    const float* Wa = (const float*)d_in[3];
    const float* Wb = (const float*)d_in[4];
    float* out = (float*)d_out;

    int T = in_sizes[1] / NE;           // 8192
    if (T > T_MAX) return;
    int nblk = (T + 255) / 256;

    static int smem_set = 0;
    int smemA = 2 * WBUF;               // 32 KB
    if (!smem_set) {
        cudaFuncSetAttribute(k_phaseA, cudaFuncAttributeMaxDynamicSharedMemorySize, smemA);
        smem_set = 1;
    }

    k_prep_route<<<192 + nblk, 256>>>(Wa, Wb, la, lb, T);
    launch_pdl(k_phaseA, dim3(NPAIR, 16), dim3(256), (size_t)smemA, x);
    launch_pdl(k_phaseB, dim3(NPAIR, DOUT / 512, 4), dim3(128), (size_t)0, out);
    launch_pdl(k_aux, dim3(1), dim3(256), (size_t)0, out + (size_t)out_size - 2, T, nblk);
}